// round 4
// baseline (speedup 1.0000x reference)
#include <cuda_runtime.h>

#define HIDDEN 768
#define FF     3072
#define NSEQ   128
#define TOKENS 65536
#define TOKB   64
#define SPLIT1 6      // gemm1 K-split: 768/6 = 128
#define SPLIT2 24     // gemm2 K-split: 3072/24 = 128
#define BK     16

// ---------------- scratch (device globals: no allocation) ----------------
__device__ float g_means[NSEQ * HIDDEN];   // pooled means (atomic target)
__device__ float g_h1[NSEQ * FF];          // dense1 output (atomic target)
__device__ float g_h2[NSEQ * HIDDEN];      // dense2 output (atomic target)

// ---------------- segment mean pooling ----------------
__global__ __launch_bounds__(192) void pool_kernel(const float* __restrict__ hs,
                                                   const int* __restrict__ lens) {
    __shared__ int   sl[NSEQ];
    __shared__ int   segof[TOKB];
    __shared__ float sinv[NSEQ];

    int tid = threadIdx.x;
    if (tid < NSEQ) {
        int l = lens[tid];
        sl[tid]   = l;
        sinv[tid] = 1.0f / (float)l;
    }
    __syncthreads();
    #pragma unroll
    for (int off = 1; off < NSEQ; off <<= 1) {
        int v = 0;
        if (tid < NSEQ && tid >= off) v = sl[tid - off];
        __syncthreads();
        if (tid < NSEQ) sl[tid] += v;
        __syncthreads();
    }

    int t0 = blockIdx.x * TOKB;
    if (tid < TOKB) {
        int t = t0 + tid;
        int lo = 0, hi = NSEQ - 1;
        while (lo < hi) {
            int mid = (lo + hi) >> 1;
            if (sl[mid] > t) hi = mid; else lo = mid + 1;
        }
        segof[tid] = lo;
    }
    __syncthreads();

    const float4* h4 = (const float4*)hs + (size_t)t0 * (HIDDEN / 4) + tid;

    int i = 0;
    while (i < TOKB) {
        int s = segof[i];
        int j = i + 1;
        while (j < TOKB && segof[j] == s) j++;    // uniform per block

        float4 a0 = make_float4(0.f, 0.f, 0.f, 0.f);
        float4 a1 = a0, a2 = a0, a3 = a0;
        int ii = i;
        for (; ii + 4 <= j; ii += 4) {
            float4 v0 = h4[(size_t)(ii + 0) * (HIDDEN / 4)];
            float4 v1 = h4[(size_t)(ii + 1) * (HIDDEN / 4)];
            float4 v2 = h4[(size_t)(ii + 2) * (HIDDEN / 4)];
            float4 v3 = h4[(size_t)(ii + 3) * (HIDDEN / 4)];
            a0.x += v0.x; a0.y += v0.y; a0.z += v0.z; a0.w += v0.w;
            a1.x += v1.x; a1.y += v1.y; a1.z += v1.z; a1.w += v1.w;
            a2.x += v2.x; a2.y += v2.y; a2.z += v2.z; a2.w += v2.w;
            a3.x += v3.x; a3.y += v3.y; a3.z += v3.z; a3.w += v3.w;
        }
        for (; ii < j; ii++) {
            float4 v = h4[(size_t)ii * (HIDDEN / 4)];
            a0.x += v.x; a0.y += v.y; a0.z += v.z; a0.w += v.w;
        }
        float inv = sinv[s];
        float rx = (a0.x + a1.x + a2.x + a3.x) * inv;
        float ry = (a0.y + a1.y + a2.y + a3.y) * inv;
        float rz = (a0.z + a1.z + a2.z + a3.z) * inv;
        float rw = (a0.w + a1.w + a2.w + a3.w) * inv;
        float* dst = &g_means[s * HIDDEN + tid * 4];
        atomicAdd(dst + 0, rx); atomicAdd(dst + 1, ry);
        atomicAdd(dst + 2, rz); atomicAdd(dst + 3, rw);
        i = j;
    }
}

// ---------------- packed f32x2 FMA ----------------
union U64 {
    float2 f2;
    unsigned long long u;
};

__device__ __forceinline__ void ffma2(U64& d, U64 a, U64 b) {
    asm("fma.rn.f32x2 %0, %1, %2, %0;" : "+l"(d.u) : "l"(a.u), "l"(b.u));
}

// ---- double-buffered NT GEMM core: block tile [128, 64], BK=16, micro 8x4 ----
// A: [128, ldA] K-contiguous; B: [N, ldB] K-contiguous. 256 threads (16x16).
__device__ __forceinline__ void gemm_core(
    const float* __restrict__ A, const float* __restrict__ B,
    int ldA, int ldB, int n0, int k0, int kIters, U64 (&c)[8][4])
{
    __shared__ float2 As[2][8][130];   // [buf][k2][m], padded
    __shared__ float2 Bs[2][8][66];    // [buf][k2][n], padded

    int tid = threadIdx.x;
    int q   = tid & 3;          // float4 index within 16-float K chunk
    int row = tid >> 2;         // 0..63

    const float* pa0 = A + (size_t)row * ldA + k0 + q * 4;
    const float* pa1 = pa0 + (size_t)64 * ldA;
    const float* pb  = B + (size_t)(n0 + row) * ldB + k0 + q * 4;

    float4 va0 = *(const float4*)pa0;
    float4 va1 = *(const float4*)pa1;
    float4 vb  = *(const float4*)pb;

    int tx = tid & 15, ty = tid >> 4;

    for (int kt = 0; kt < kIters; kt++) {
        int buf = kt & 1;
        As[buf][q * 2 + 0][row]      = make_float2(va0.x, va0.y);
        As[buf][q * 2 + 1][row]      = make_float2(va0.z, va0.w);
        As[buf][q * 2 + 0][row + 64] = make_float2(va1.x, va1.y);
        As[buf][q * 2 + 1][row + 64] = make_float2(va1.z, va1.w);
        Bs[buf][q * 2 + 0][row]      = make_float2(vb.x, vb.y);
        Bs[buf][q * 2 + 1][row]      = make_float2(vb.z, vb.w);
        __syncthreads();

        if (kt + 1 < kIters) {
            int off = (kt + 1) * BK;
            va0 = *(const float4*)(pa0 + off);
            va1 = *(const float4*)(pa1 + off);
            vb  = *(const float4*)(pb + off);
        }

        #pragma unroll
        for (int k2 = 0; k2 < 8; k2++) {
            U64 a[8], b[4];
            #pragma unroll
            for (int ii = 0; ii < 4; ii++) {
                float4 v = *(const float4*)(&As[buf][k2][ty * 8 + 2 * ii]);
                a[2 * ii + 0].f2 = make_float2(v.x, v.y);
                a[2 * ii + 1].f2 = make_float2(v.z, v.w);
            }
            #pragma unroll
            for (int jj = 0; jj < 2; jj++) {
                float4 v = *(const float4*)(&Bs[buf][k2][tx * 4 + 2 * jj]);
                b[2 * jj + 0].f2 = make_float2(v.x, v.y);
                b[2 * jj + 1].f2 = make_float2(v.z, v.w);
            }
            #pragma unroll
            for (int i = 0; i < 8; i++)
                #pragma unroll
                for (int j = 0; j < 4; j++)
                    ffma2(c[i][j], a[i], b[j]);
        }
        // single barrier per iter: double buffer makes next writes safe
    }
}

// GEMM1: g_h1 += means @ W1^T (K chunk 128). grid (48, SPLIT1)
__global__ __launch_bounds__(256, 2) void gemm1_kernel(const float* __restrict__ W1) {
    U64 c[8][4];
    #pragma unroll
    for (int i = 0; i < 8; i++)
        #pragma unroll
        for (int j = 0; j < 4; j++) c[i][j].f2 = make_float2(0.f, 0.f);

    int n0 = blockIdx.x * 64, kz = blockIdx.y;
    gemm_core(g_means, W1, HIDDEN, HIDDEN, n0, kz * (HIDDEN / SPLIT1),
              (HIDDEN / SPLIT1) / BK, c);

    int tx = threadIdx.x & 15, ty = threadIdx.x >> 4;
    #pragma unroll
    for (int i = 0; i < 8; i++) {
        int m = ty * 8 + i;
        float* dst = &g_h1[(size_t)m * FF + n0 + tx * 4];
        atomicAdd(dst + 0, c[i][0].f2.x + c[i][0].f2.y);
        atomicAdd(dst + 1, c[i][1].f2.x + c[i][1].f2.y);
        atomicAdd(dst + 2, c[i][2].f2.x + c[i][2].f2.y);
        atomicAdd(dst + 3, c[i][3].f2.x + c[i][3].f2.y);
    }
}

// GEMM2: g_h2 += h1 @ W2^T (K chunk 128). grid (12, SPLIT2)
__global__ __launch_bounds__(256, 2) void gemm2_kernel(const float* __restrict__ W2) {
    U64 c[8][4];
    #pragma unroll
    for (int i = 0; i < 8; i++)
        #pragma unroll
        for (int j = 0; j < 4; j++) c[i][j].f2 = make_float2(0.f, 0.f);

    int n0 = blockIdx.x * 64, kz = blockIdx.y;
    gemm_core(g_h1, W2, FF, FF, n0, kz * (FF / SPLIT2),
              (FF / SPLIT2) / BK, c);

    int tx = threadIdx.x & 15, ty = threadIdx.x >> 4;
    #pragma unroll
    for (int i = 0; i < 8; i++) {
        int m = ty * 8 + i;
        float* dst = &g_h2[(size_t)m * HIDDEN + n0 + tx * 4];
        atomicAdd(dst + 0, c[i][0].f2.x + c[i][0].f2.y);
        atomicAdd(dst + 1, c[i][1].f2.x + c[i][1].f2.y);
        atomicAdd(dst + 2, c[i][2].f2.x + c[i][2].f2.y);
        atomicAdd(dst + 3, c[i][3].f2.x + c[i][3].f2.y);
    }
}

// ---------------- L2 normalize rows ----------------
__global__ __launch_bounds__(256) void norm_kernel(float* __restrict__ out) {
    int s = blockIdx.x, tid = threadIdx.x;
    float val[3];
    #pragma unroll
    for (int k = 0; k < 3; k++) val[k] = g_h2[s * HIDDEN + tid + k * 256];
    float ss = val[0] * val[0] + val[1] * val[1] + val[2] * val[2];

    __shared__ float red[8];
    #pragma unroll
    for (int o = 16; o > 0; o >>= 1) ss += __shfl_xor_sync(0xffffffffu, ss, o);
    if ((tid & 31) == 0) red[tid >> 5] = ss;
    __syncthreads();
    __shared__ float sInv;
    if (tid == 0) {
        float tot = 0.f;
        #pragma unroll
        for (int w = 0; w < 8; w++) tot += red[w];
        sInv = 1.0f / fmaxf(sqrtf(tot), 1e-12f);
    }
    __syncthreads();
    float inv = sInv;
    #pragma unroll
    for (int k = 0; k < 3; k++)
        out[s * HIDDEN + tid + k * 256] = val[k] * inv;
}

// ---------------- launch ----------------
extern "C" void kernel_launch(void* const* d_in, const int* in_sizes, int n_in,
                              void* d_out, int out_size) {
    const float* hs   = (const float*)d_in[0];   // [65536, 768] fp32
    const int*   lens = (const int*)  d_in[1];   // [128] int32
    const float* W1   = (const float*)d_in[2];   // [3072, 768] fp32
    const float* W2   = (const float*)d_in[3];   // [768, 3072] fp32
    float* out = (float*)d_out;                  // [128, 768] fp32

    void *pMeans = 0, *pH1 = 0, *pH2 = 0;
    cudaGetSymbolAddress(&pMeans, g_means);
    cudaGetSymbolAddress(&pH1,    g_h1);
    cudaGetSymbolAddress(&pH2,    g_h2);
    cudaMemsetAsync(pMeans, 0, NSEQ * HIDDEN * sizeof(float));
    cudaMemsetAsync(pH1,    0, NSEQ * FF     * sizeof(float));
    cudaMemsetAsync(pH2,    0, NSEQ * HIDDEN * sizeof(float));

    pool_kernel<<<TOKENS / TOKB, 192>>>(hs, lens);
    gemm1_kernel<<<dim3(FF / 64, SPLIT1), 256>>>(W1);
    gemm2_kernel<<<dim3(HIDDEN / 64, SPLIT2), 256>>>(W2);
    norm_kernel<<<NSEQ, 256>>>(out);
}

// round 5
// speedup vs baseline: 1.1134x; 1.1134x over previous
#include <cuda_runtime.h>

#define HIDDEN 768
#define FF     3072
#define NSEQ   128
#define TOKENS 65536
#define TOKB   32
#define SPLIT1 6      // gemm1 K-split: 768/6 = 128
#define SPLIT2 24     // gemm2 K-split: 3072/24 = 128
#define BK     16

// ---------------- scratch (device globals: no allocation) ----------------
__device__ float g_means[NSEQ * HIDDEN];            // pooled means (atomic target)
__device__ float g_h1p[SPLIT1 * NSEQ * FF];         // gemm1 partials
__device__ float g_h1[NSEQ * FF];                   // reduced dense1 output
__device__ float g_h2p[SPLIT2 * NSEQ * HIDDEN];     // gemm2 partials

// ---------------- segment mean pooling ----------------
__global__ __launch_bounds__(192) void pool_kernel(const float* __restrict__ hs,
                                                   const int* __restrict__ lens) {
    __shared__ int   sl[NSEQ];
    __shared__ int   segof[TOKB];
    __shared__ float sinv[NSEQ];

    int tid = threadIdx.x;
    if (tid < NSEQ) {
        int l = lens[tid];
        sl[tid]   = l;
        sinv[tid] = 1.0f / (float)l;
    }
    __syncthreads();
    #pragma unroll
    for (int off = 1; off < NSEQ; off <<= 1) {
        int v = 0;
        if (tid < NSEQ && tid >= off) v = sl[tid - off];
        __syncthreads();
        if (tid < NSEQ) sl[tid] += v;
        __syncthreads();
    }

    int t0 = blockIdx.x * TOKB;
    if (tid < TOKB) {
        int t = t0 + tid;
        int lo = 0, hi = NSEQ - 1;
        while (lo < hi) {
            int mid = (lo + hi) >> 1;
            if (sl[mid] > t) hi = mid; else lo = mid + 1;
        }
        segof[tid] = lo;
    }
    __syncthreads();

    const float4* h4 = (const float4*)hs + (size_t)t0 * (HIDDEN / 4) + tid;

    if (segof[0] == segof[TOKB - 1]) {
        // ---- fast path: whole block in one segment, branch-free, high MLP ----
        int s = segof[0];
        float4 a0 = make_float4(0.f, 0.f, 0.f, 0.f);
        float4 a1 = a0, a2 = a0, a3 = a0;
        #pragma unroll
        for (int i = 0; i < TOKB; i += 4) {
            float4 v0 = h4[(size_t)(i + 0) * (HIDDEN / 4)];
            float4 v1 = h4[(size_t)(i + 1) * (HIDDEN / 4)];
            float4 v2 = h4[(size_t)(i + 2) * (HIDDEN / 4)];
            float4 v3 = h4[(size_t)(i + 3) * (HIDDEN / 4)];
            a0.x += v0.x; a0.y += v0.y; a0.z += v0.z; a0.w += v0.w;
            a1.x += v1.x; a1.y += v1.y; a1.z += v1.z; a1.w += v1.w;
            a2.x += v2.x; a2.y += v2.y; a2.z += v2.z; a2.w += v2.w;
            a3.x += v3.x; a3.y += v3.y; a3.z += v3.z; a3.w += v3.w;
        }
        float inv = sinv[s];
        float* dst = &g_means[s * HIDDEN + tid * 4];
        atomicAdd(dst + 0, (a0.x + a1.x + a2.x + a3.x) * inv);
        atomicAdd(dst + 1, (a0.y + a1.y + a2.y + a3.y) * inv);
        atomicAdd(dst + 2, (a0.z + a1.z + a2.z + a3.z) * inv);
        atomicAdd(dst + 3, (a0.w + a1.w + a2.w + a3.w) * inv);
    } else {
        // ---- boundary path: per-token segment tracking ----
        float4 acc = make_float4(0.f, 0.f, 0.f, 0.f);
        int cur = segof[0];
        #pragma unroll
        for (int i = 0; i < TOKB; i++) {
            float4 v = h4[(size_t)i * (HIDDEN / 4)];
            int s = segof[i];
            if (s != cur) {
                float inv = sinv[cur];
                float* dst = &g_means[cur * HIDDEN + tid * 4];
                atomicAdd(dst + 0, acc.x * inv); atomicAdd(dst + 1, acc.y * inv);
                atomicAdd(dst + 2, acc.z * inv); atomicAdd(dst + 3, acc.w * inv);
                acc = make_float4(0.f, 0.f, 0.f, 0.f);
                cur = s;
            }
            acc.x += v.x; acc.y += v.y; acc.z += v.z; acc.w += v.w;
        }
        float inv = sinv[cur];
        float* dst = &g_means[cur * HIDDEN + tid * 4];
        atomicAdd(dst + 0, acc.x * inv); atomicAdd(dst + 1, acc.y * inv);
        atomicAdd(dst + 2, acc.z * inv); atomicAdd(dst + 3, acc.w * inv);
    }
}

// ---------------- packed f32x2 FMA ----------------
union U64 {
    float2 f2;
    unsigned long long u;
};

__device__ __forceinline__ void ffma2(U64& d, U64 a, U64 b) {
    asm("fma.rn.f32x2 %0, %1, %2, %0;" : "+l"(d.u) : "l"(a.u), "l"(b.u));
}

// ---- double-buffered NT GEMM core: block tile [128, 64], BK=16, micro 8x4 ----
// A: [128, ldA] K-contiguous; B: [N, ldB] K-contiguous. 256 threads (16x16).
__device__ __forceinline__ void gemm_core(
    const float* __restrict__ A, const float* __restrict__ B,
    int ldA, int ldB, int n0, int k0, int kIters, U64 (&c)[8][4])
{
    __shared__ float2 As[2][8][130];   // [buf][k2][m], padded
    __shared__ float2 Bs[2][8][66];    // [buf][k2][n], padded

    int tid = threadIdx.x;
    int q   = tid & 3;          // float4 index within 16-float K chunk
    int row = tid >> 2;         // 0..63

    const float* pa0 = A + (size_t)row * ldA + k0 + q * 4;
    const float* pa1 = pa0 + (size_t)64 * ldA;
    const float* pb  = B + (size_t)(n0 + row) * ldB + k0 + q * 4;

    float4 va0 = *(const float4*)pa0;
    float4 va1 = *(const float4*)pa1;
    float4 vb  = *(const float4*)pb;

    int tx = tid & 15, ty = tid >> 4;

    for (int kt = 0; kt < kIters; kt++) {
        int buf = kt & 1;
        As[buf][q * 2 + 0][row]      = make_float2(va0.x, va0.y);
        As[buf][q * 2 + 1][row]      = make_float2(va0.z, va0.w);
        As[buf][q * 2 + 0][row + 64] = make_float2(va1.x, va1.y);
        As[buf][q * 2 + 1][row + 64] = make_float2(va1.z, va1.w);
        Bs[buf][q * 2 + 0][row]      = make_float2(vb.x, vb.y);
        Bs[buf][q * 2 + 1][row]      = make_float2(vb.z, vb.w);
        __syncthreads();

        if (kt + 1 < kIters) {
            int off = (kt + 1) * BK;
            va0 = *(const float4*)(pa0 + off);
            va1 = *(const float4*)(pa1 + off);
            vb  = *(const float4*)(pb + off);
        }

        #pragma unroll
        for (int k2 = 0; k2 < 8; k2++) {
            U64 a[8], b[4];
            #pragma unroll
            for (int ii = 0; ii < 4; ii++) {
                float4 v = *(const float4*)(&As[buf][k2][ty * 8 + 2 * ii]);
                a[2 * ii + 0].f2 = make_float2(v.x, v.y);
                a[2 * ii + 1].f2 = make_float2(v.z, v.w);
            }
            #pragma unroll
            for (int jj = 0; jj < 2; jj++) {
                float4 v = *(const float4*)(&Bs[buf][k2][tx * 4 + 2 * jj]);
                b[2 * jj + 0].f2 = make_float2(v.x, v.y);
                b[2 * jj + 1].f2 = make_float2(v.z, v.w);
            }
            #pragma unroll
            for (int i = 0; i < 8; i++)
                #pragma unroll
                for (int j = 0; j < 4; j++)
                    ffma2(c[i][j], a[i], b[j]);
        }
        // single barrier per iter: double buffer makes next writes safe
    }
}

// GEMM1: h1p[kz] = means @ W1^T over K chunk 128. grid (48, SPLIT1)
__global__ __launch_bounds__(256, 2) void gemm1_kernel(const float* __restrict__ W1) {
    U64 c[8][4];
    #pragma unroll
    for (int i = 0; i < 8; i++)
        #pragma unroll
        for (int j = 0; j < 4; j++) c[i][j].f2 = make_float2(0.f, 0.f);

    int n0 = blockIdx.x * 64, kz = blockIdx.y;
    gemm_core(g_means, W1, HIDDEN, HIDDEN, n0, kz * (HIDDEN / SPLIT1),
              (HIDDEN / SPLIT1) / BK, c);

    float* C = g_h1p + (size_t)kz * NSEQ * FF;
    int tx = threadIdx.x & 15, ty = threadIdx.x >> 4;
    #pragma unroll
    for (int i = 0; i < 8; i++) {
        int m = ty * 8 + i;
        float4 v = make_float4(c[i][0].f2.x + c[i][0].f2.y,
                               c[i][1].f2.x + c[i][1].f2.y,
                               c[i][2].f2.x + c[i][2].f2.y,
                               c[i][3].f2.x + c[i][3].f2.y);
        *(float4*)&C[(size_t)m * FF + n0 + tx * 4] = v;
    }
}

// reduce gemm1 partials: g_h1 = sum over SPLIT1
__global__ __launch_bounds__(256) void reduce1_kernel() {
    int i = blockIdx.x * blockDim.x + threadIdx.x;   // float4 index
    const float4* p = (const float4*)g_h1p;
    float4 acc = p[i];
    #pragma unroll
    for (int s = 1; s < SPLIT1; s++) {
        float4 v = p[i + (size_t)s * (NSEQ * FF / 4)];
        acc.x += v.x; acc.y += v.y; acc.z += v.z; acc.w += v.w;
    }
    ((float4*)g_h1)[i] = acc;
}

// GEMM2: h2p[kz] = h1 @ W2^T over K chunk 128. grid (12, SPLIT2)
__global__ __launch_bounds__(256, 2) void gemm2_kernel(const float* __restrict__ W2) {
    U64 c[8][4];
    #pragma unroll
    for (int i = 0; i < 8; i++)
        #pragma unroll
        for (int j = 0; j < 4; j++) c[i][j].f2 = make_float2(0.f, 0.f);

    int n0 = blockIdx.x * 64, kz = blockIdx.y;
    gemm_core(g_h1, W2, FF, FF, n0, kz * (FF / SPLIT2),
              (FF / SPLIT2) / BK, c);

    float* C = g_h2p + (size_t)kz * NSEQ * HIDDEN;
    int tx = threadIdx.x & 15, ty = threadIdx.x >> 4;
    #pragma unroll
    for (int i = 0; i < 8; i++) {
        int m = ty * 8 + i;
        float4 v = make_float4(c[i][0].f2.x + c[i][0].f2.y,
                               c[i][1].f2.x + c[i][1].f2.y,
                               c[i][2].f2.x + c[i][2].f2.y,
                               c[i][3].f2.x + c[i][3].f2.y);
        *(float4*)&C[(size_t)m * HIDDEN + n0 + tx * 4] = v;
    }
}

// ---------------- reduce gemm2 partials + L2 normalize (192 thr, float4) ----------------
__global__ __launch_bounds__(192) void norm_kernel(float* __restrict__ out) {
    int s = blockIdx.x, tid = threadIdx.x;   // 0..191, one float4 each
    float4 acc = make_float4(0.f, 0.f, 0.f, 0.f);
    #pragma unroll
    for (int z = 0; z < SPLIT2; z++) {
        const float4* p = (const float4*)(g_h2p + (size_t)z * NSEQ * HIDDEN + s * HIDDEN);
        float4 v = p[tid];
        acc.x += v.x; acc.y += v.y; acc.z += v.z; acc.w += v.w;
    }
    float ss = acc.x * acc.x + acc.y * acc.y + acc.z * acc.z + acc.w * acc.w;

    __shared__ float red[6];
    #pragma unroll
    for (int o = 16; o > 0; o >>= 1) ss += __shfl_xor_sync(0xffffffffu, ss, o);
    if ((tid & 31) == 0) red[tid >> 5] = ss;
    __syncthreads();
    __shared__ float sInv;
    if (tid == 0) {
        float tot = 0.f;
        #pragma unroll
        for (int w = 0; w < 6; w++) tot += red[w];
        sInv = 1.0f / fmaxf(sqrtf(tot), 1e-12f);
    }
    __syncthreads();
    float inv = sInv;
    float4 r = make_float4(acc.x * inv, acc.y * inv, acc.z * inv, acc.w * inv);
    ((float4*)(out + s * HIDDEN))[tid] = r;
}

// ---------------- launch ----------------
extern "C" void kernel_launch(void* const* d_in, const int* in_sizes, int n_in,
                              void* d_out, int out_size) {
    const float* hs   = (const float*)d_in[0];   // [65536, 768] fp32
    const int*   lens = (const int*)  d_in[1];   // [128] int32
    const float* W1   = (const float*)d_in[2];   // [3072, 768] fp32
    const float* W2   = (const float*)d_in[3];   // [768, 3072] fp32
    float* out = (float*)d_out;                  // [128, 768] fp32

    void* pMeans = 0;
    cudaGetSymbolAddress(&pMeans, g_means);
    cudaMemsetAsync(pMeans, 0, NSEQ * HIDDEN * sizeof(float));

    pool_kernel<<<TOKENS / TOKB, 192>>>(hs, lens);
    gemm1_kernel<<<dim3(FF / 64, SPLIT1), 256>>>(W1);
    reduce1_kernel<<<(NSEQ * FF / 4) / 256, 256>>>();
    gemm2_kernel<<<dim3(HIDDEN / 64, SPLIT2), 256>>>(W2);
    norm_kernel<<<NSEQ, 192>>>(out);
}

// round 7
// speedup vs baseline: 1.1627x; 1.0443x over previous
#include <cuda_runtime.h>
#include <cuda_bf16.h>

#define HIDDEN 768
#define FF     3072
#define NSEQ   128
#define TOKENS 65536
#define TOKB   32
#define SPLIT1 4      // gemm1 K-split: 768/4 = 192
#define SPLIT2 16     // gemm2 K-split: 3072/16 = 192
#define KC     32     // K floats per chunk
#define CHUNKS 6      // 6*32 = 192 K per CTA
#define RS     80     // smem row stride in bytes (32 bf16 = 64B data + pad)

// ---------------- scratch (device globals: no allocation) ----------------
__device__ float g_means[NSEQ * HIDDEN];        // pooled means (atomic target)
__device__ float g_h1p[SPLIT1 * NSEQ * FF];     // gemm1 partials
__device__ float g_h2[NSEQ * HIDDEN];           // gemm2 atomic target

// ---------------- segment mean pooling (round-5 proven) ----------------
__global__ __launch_bounds__(192) void pool_kernel(const float* __restrict__ hs,
                                                   const int* __restrict__ lens) {
    __shared__ int   sl[NSEQ];
    __shared__ int   segof[TOKB];
    __shared__ float sinv[NSEQ];

    int tid = threadIdx.x;
    if (tid < NSEQ) {
        int l = lens[tid];
        sl[tid]   = l;
        sinv[tid] = 1.0f / (float)l;
    }
    __syncthreads();
    #pragma unroll
    for (int off = 1; off < NSEQ; off <<= 1) {
        int v = 0;
        if (tid < NSEQ && tid >= off) v = sl[tid - off];
        __syncthreads();
        if (tid < NSEQ) sl[tid] += v;
        __syncthreads();
    }

    int t0 = blockIdx.x * TOKB;
    if (tid < TOKB) {
        int t = t0 + tid;
        int lo = 0, hi = NSEQ - 1;
        while (lo < hi) {
            int mid = (lo + hi) >> 1;
            if (sl[mid] > t) hi = mid; else lo = mid + 1;
        }
        segof[tid] = lo;
    }
    __syncthreads();

    const float4* h4 = (const float4*)hs + (size_t)t0 * (HIDDEN / 4) + tid;

    if (segof[0] == segof[TOKB - 1]) {
        int s = segof[0];
        float4 a0 = make_float4(0.f, 0.f, 0.f, 0.f);
        float4 a1 = a0, a2 = a0, a3 = a0;
        #pragma unroll
        for (int i = 0; i < TOKB; i += 4) {
            float4 v0 = h4[(size_t)(i + 0) * (HIDDEN / 4)];
            float4 v1 = h4[(size_t)(i + 1) * (HIDDEN / 4)];
            float4 v2 = h4[(size_t)(i + 2) * (HIDDEN / 4)];
            float4 v3 = h4[(size_t)(i + 3) * (HIDDEN / 4)];
            a0.x += v0.x; a0.y += v0.y; a0.z += v0.z; a0.w += v0.w;
            a1.x += v1.x; a1.y += v1.y; a1.z += v1.z; a1.w += v1.w;
            a2.x += v2.x; a2.y += v2.y; a2.z += v2.z; a2.w += v2.w;
            a3.x += v3.x; a3.y += v3.y; a3.z += v3.z; a3.w += v3.w;
        }
        float inv = sinv[s];
        float* dst = &g_means[s * HIDDEN + tid * 4];
        atomicAdd(dst + 0, (a0.x + a1.x + a2.x + a3.x) * inv);
        atomicAdd(dst + 1, (a0.y + a1.y + a2.y + a3.y) * inv);
        atomicAdd(dst + 2, (a0.z + a1.z + a2.z + a3.z) * inv);
        atomicAdd(dst + 3, (a0.w + a1.w + a2.w + a3.w) * inv);
    } else {
        float4 acc = make_float4(0.f, 0.f, 0.f, 0.f);
        int cur = segof[0];
        #pragma unroll
        for (int i = 0; i < TOKB; i++) {
            float4 v = h4[(size_t)i * (HIDDEN / 4)];
            int s = segof[i];
            if (s != cur) {
                float inv = sinv[cur];
                float* dst = &g_means[cur * HIDDEN + tid * 4];
                atomicAdd(dst + 0, acc.x * inv); atomicAdd(dst + 1, acc.y * inv);
                atomicAdd(dst + 2, acc.z * inv); atomicAdd(dst + 3, acc.w * inv);
                acc = make_float4(0.f, 0.f, 0.f, 0.f);
                cur = s;
            }
            acc.x += v.x; acc.y += v.y; acc.z += v.z; acc.w += v.w;
        }
        float inv = sinv[cur];
        float* dst = &g_means[cur * HIDDEN + tid * 4];
        atomicAdd(dst + 0, acc.x * inv); atomicAdd(dst + 1, acc.y * inv);
        atomicAdd(dst + 2, acc.z * inv); atomicAdd(dst + 3, acc.w * inv);
    }
}

// ---------------- bf16 hi/lo split of a float4, packed as 2x(2x bf16) ----------------
__device__ __forceinline__ void split4(float4 v, unsigned long long& hi, unsigned long long& lo) {
    __nv_bfloat16 h0 = __float2bfloat16(v.x), h1 = __float2bfloat16(v.y);
    __nv_bfloat16 h2 = __float2bfloat16(v.z), h3 = __float2bfloat16(v.w);
    __nv_bfloat16 l0 = __float2bfloat16(v.x - __bfloat162float(h0));
    __nv_bfloat16 l1 = __float2bfloat16(v.y - __bfloat162float(h1));
    __nv_bfloat16 l2 = __float2bfloat16(v.z - __bfloat162float(h2));
    __nv_bfloat16 l3 = __float2bfloat16(v.w - __bfloat162float(h3));
    hi = (unsigned long long)__bfloat16_as_ushort(h0)
       | ((unsigned long long)__bfloat16_as_ushort(h1) << 16)
       | ((unsigned long long)__bfloat16_as_ushort(h2) << 32)
       | ((unsigned long long)__bfloat16_as_ushort(h3) << 48);
    lo = (unsigned long long)__bfloat16_as_ushort(l0)
       | ((unsigned long long)__bfloat16_as_ushort(l1) << 16)
       | ((unsigned long long)__bfloat16_as_ushort(l2) << 32)
       | ((unsigned long long)__bfloat16_as_ushort(l3) << 48);
}

#define MMA_BF16(C, A0, A1, A2, A3, B0, B1)                                          \
    asm volatile(                                                                    \
        "mma.sync.aligned.m16n8k16.row.col.f32.bf16.bf16.f32 "                       \
        "{%0,%1,%2,%3}, {%4,%5,%6,%7}, {%8,%9}, {%0,%1,%2,%3};"                      \
        : "+f"((C)[0]), "+f"((C)[1]), "+f"((C)[2]), "+f"((C)[3])                     \
        : "r"(A0), "r"(A1), "r"(A2), "r"(A3), "r"(B0), "r"(B1))

// smem layout (bytes): Ahi[128*RS] Alo[128*RS] Bhi[64*RS] Blo[64*RS] = 30720 B
#define SAHI 0
#define SALO (128 * RS)
#define SBHI (256 * RS)
#define SBLO (256 * RS + 64 * RS)

// ====== mma.sync GEMM: D[128, 64/CTA] = fp32(A[128,K]) @ B[N,K]^T, 3-pass bf16 ======
// grid (Ntiles, SPLIT). A summed over NSUM partial buffers (aStride apart).
template<int NSUM, bool ATOMIC>
__global__ __launch_bounds__(256) void mma_gemm(
    const float* __restrict__ A, const float* __restrict__ B, float* __restrict__ C,
    int ldA, int ldB, int ldC, long long aStride, long long cStride)
{
    __shared__ __align__(128) unsigned char sm[30720];

    int tid  = threadIdx.x;
    int wid  = tid >> 5, lane = tid & 31;
    int g    = lane >> 2, tg = lane & 3;
    int wm   = wid >> 1, wn = wid & 1;          // warp grid 4 (M) x 2 (N)
    int m0   = wm * 32;                          // warp M base within 128
    int nb   = wn * 32;                          // warp N base within 64

    int n0blk = blockIdx.x * 64;
    int k0    = blockIdx.y * (CHUNKS * KC);

    // conversion-load indices: A 4x float4/thread, B 2x float4/thread
    int ar[4], aq[4], br[2], bq[2];
    #pragma unroll
    for (int t = 0; t < 4; t++) { int idx = tid + t * 256; ar[t] = idx >> 3; aq[t] = idx & 7; }
    #pragma unroll
    for (int t = 0; t < 2; t++) { int idx = tid + t * 256; br[t] = idx >> 3; bq[t] = idx & 7; }

    float c[2][4][4];
    #pragma unroll
    for (int i = 0; i < 2; i++)
        #pragma unroll
        for (int j = 0; j < 4; j++)
            #pragma unroll
            for (int r = 0; r < 4; r++) c[i][j][r] = 0.f;

    // prefetch chunk 0
    float4 av[4], bv[2];
    #pragma unroll
    for (int t = 0; t < 4; t++) {
        const float* p = A + (size_t)ar[t] * ldA + k0 + aq[t] * 4;
        float4 v = *(const float4*)p;
        #pragma unroll
        for (int s = 1; s < NSUM; s++) {
            float4 w = *(const float4*)(p + (size_t)s * aStride);
            v.x += w.x; v.y += w.y; v.z += w.z; v.w += w.w;
        }
        av[t] = v;
    }
    #pragma unroll
    for (int t = 0; t < 2; t++)
        bv[t] = *(const float4*)(B + (size_t)(n0blk + br[t]) * ldB + k0 + bq[t] * 4);

    for (int ch = 0; ch < CHUNKS; ch++) {
        // convert + store current chunk
        #pragma unroll
        for (int t = 0; t < 4; t++) {
            unsigned long long hi, lo;
            split4(av[t], hi, lo);
            int off = ar[t] * RS + aq[t] * 8;
            *(unsigned long long*)(sm + SAHI + off) = hi;
            *(unsigned long long*)(sm + SALO + off) = lo;
        }
        #pragma unroll
        for (int t = 0; t < 2; t++) {
            unsigned long long hi, lo;
            split4(bv[t], hi, lo);
            int off = br[t] * RS + bq[t] * 8;
            *(unsigned long long*)(sm + SBHI + off) = hi;
            *(unsigned long long*)(sm + SBLO + off) = lo;
        }
        __syncthreads();

        // prefetch next chunk (overlaps with MMA below)
        if (ch + 1 < CHUNKS) {
            int kk = k0 + (ch + 1) * KC;
            #pragma unroll
            for (int t = 0; t < 4; t++) {
                const float* p = A + (size_t)ar[t] * ldA + kk + aq[t] * 4;
                float4 v = *(const float4*)p;
                #pragma unroll
                for (int s = 1; s < NSUM; s++) {
                    float4 w = *(const float4*)(p + (size_t)s * aStride);
                    v.x += w.x; v.y += w.y; v.z += w.z; v.w += w.w;
                }
                av[t] = v;
            }
            #pragma unroll
            for (int t = 0; t < 2; t++)
                bv[t] = *(const float4*)(B + (size_t)(n0blk + br[t]) * ldB + kk + bq[t] * 4);
        }

        // compute: 2 k16 steps x (2 m-frags x 4 n-frags) x 3 passes
        #pragma unroll
        for (int ks = 0; ks < 2; ks++) {
            unsigned Ah[2][4], Al[2][4], Bh[4][2], Bl[4][2];
            #pragma unroll
            for (int i = 0; i < 2; i++) {
                int off = (m0 + i * 16 + g) * RS + ks * 32 + tg * 4;
                Ah[i][0] = *(const unsigned*)(sm + SAHI + off);
                Ah[i][1] = *(const unsigned*)(sm + SAHI + off + 8 * RS);
                Ah[i][2] = *(const unsigned*)(sm + SAHI + off + 16);
                Ah[i][3] = *(const unsigned*)(sm + SAHI + off + 8 * RS + 16);
                Al[i][0] = *(const unsigned*)(sm + SALO + off);
                Al[i][1] = *(const unsigned*)(sm + SALO + off + 8 * RS);
                Al[i][2] = *(const unsigned*)(sm + SALO + off + 16);
                Al[i][3] = *(const unsigned*)(sm + SALO + off + 8 * RS + 16);
            }
            #pragma unroll
            for (int j = 0; j < 4; j++) {
                int off = (nb + j * 8 + g) * RS + ks * 32 + tg * 4;
                Bh[j][0] = *(const unsigned*)(sm + SBHI + off);
                Bh[j][1] = *(const unsigned*)(sm + SBHI + off + 16);
                Bl[j][0] = *(const unsigned*)(sm + SBLO + off);
                Bl[j][1] = *(const unsigned*)(sm + SBLO + off + 16);
            }
            #pragma unroll
            for (int i = 0; i < 2; i++)
                #pragma unroll
                for (int j = 0; j < 4; j++) {
                    MMA_BF16(c[i][j], Ah[i][0], Ah[i][1], Ah[i][2], Ah[i][3], Bh[j][0], Bh[j][1]);
                    MMA_BF16(c[i][j], Ah[i][0], Ah[i][1], Ah[i][2], Ah[i][3], Bl[j][0], Bl[j][1]);
                    MMA_BF16(c[i][j], Al[i][0], Al[i][1], Al[i][2], Al[i][3], Bh[j][0], Bh[j][1]);
                }
        }
        __syncthreads();
    }

    // epilogue
    #pragma unroll
    for (int i = 0; i < 2; i++) {
        int R0 = m0 + i * 16 + g;
        int R1 = R0 + 8;
        #pragma unroll
        for (int j = 0; j < 4; j++) {
            int Cc = n0blk + nb + j * 8 + tg * 2;
            if (ATOMIC) {
                atomicAdd(&C[(size_t)R0 * ldC + Cc],     c[i][j][0]);
                atomicAdd(&C[(size_t)R0 * ldC + Cc + 1], c[i][j][1]);
                atomicAdd(&C[(size_t)R1 * ldC + Cc],     c[i][j][2]);
                atomicAdd(&C[(size_t)R1 * ldC + Cc + 1], c[i][j][3]);
            } else {
                float* base = C + (size_t)blockIdx.y * cStride;
                *(float2*)&base[(size_t)R0 * ldC + Cc] = make_float2(c[i][j][0], c[i][j][1]);
                *(float2*)&base[(size_t)R1 * ldC + Cc] = make_float2(c[i][j][2], c[i][j][3]);
            }
        }
    }
}

// ---------------- L2 normalize rows ----------------
__global__ __launch_bounds__(192) void norm_kernel(float* __restrict__ out) {
    int s = blockIdx.x, tid = threadIdx.x;   // one float4 per thread
    float4 acc = ((const float4*)(g_h2 + s * HIDDEN))[tid];
    float ss = acc.x * acc.x + acc.y * acc.y + acc.z * acc.z + acc.w * acc.w;

    __shared__ float red[6];
    #pragma unroll
    for (int o = 16; o > 0; o >>= 1) ss += __shfl_xor_sync(0xffffffffu, ss, o);
    if ((tid & 31) == 0) red[tid >> 5] = ss;
    __syncthreads();
    __shared__ float sInv;
    if (tid == 0) {
        float tot = 0.f;
        #pragma unroll
        for (int w = 0; w < 6; w++) tot += red[w];
        sInv = 1.0f / fmaxf(sqrtf(tot), 1e-12f);
    }
    __syncthreads();
    float inv = sInv;
    float4 r = make_float4(acc.x * inv, acc.y * inv, acc.z * inv, acc.w * inv);
    ((float4*)(out + s * HIDDEN))[tid] = r;
}

// ---------------- launch ----------------
extern "C" void kernel_launch(void* const* d_in, const int* in_sizes, int n_in,
                              void* d_out, int out_size) {
    const float* hs   = (const float*)d_in[0];   // [65536, 768] fp32
    const int*   lens = (const int*)  d_in[1];   // [128] int32
    const float* W1   = (const float*)d_in[2];   // [3072, 768] fp32
    const float* W2   = (const float*)d_in[3];   // [768, 3072] fp32
    float* out = (float*)d_out;                  // [128, 768] fp32

    void *pMeans = 0, *pH1p = 0, *pH2 = 0;
    cudaGetSymbolAddress(&pMeans, g_means);
    cudaGetSymbolAddress(&pH1p,   g_h1p);
    cudaGetSymbolAddress(&pH2,    g_h2);
    cudaMemsetAsync(pMeans, 0, NSEQ * HIDDEN * sizeof(float));
    cudaMemsetAsync(pH2,    0, NSEQ * HIDDEN * sizeof(float));

    pool_kernel<<<TOKENS / TOKB, 192>>>(hs, lens);

    // GEMM1: g_h1p[kz] = means @ W1^T  (K=768 = 4 x 192; 48 N-tiles)
    mma_gemm<1, false><<<dim3(FF / 64, SPLIT1), 256>>>(
        (const float*)pMeans, W1, (float*)pH1p,
        HIDDEN, HIDDEN, FF, 0, (long long)NSEQ * FF);

    // GEMM2: g_h2 += (sum of 4 h1 partials) @ W2^T  (K=3072 = 16 x 192; 12 N-tiles)
    mma_gemm<SPLIT1, true><<<dim3(HIDDEN / 64, SPLIT2), 256>>>(
        (const float*)pH1p, W2, (float*)pH2,
        FF, FF, HIDDEN, (long long)NSEQ * FF, 0);

    norm_kernel<<<NSEQ, 192>>>(out);
}

// round 8
// speedup vs baseline: 1.1816x; 1.0162x over previous
#include <cuda_runtime.h>
#include <cuda_bf16.h>

#define HIDDEN 768
#define FF     3072
#define NSEQ   128
#define TOKENS 65536
#define TOKB   32
#define SPLIT2 16     // gemm2 K-split: 3072/16 = 192
#define KC     32     // K floats per chunk
#define RS     80     // smem row stride bytes (32 bf16 = 64B + 16B pad)

// ---------------- scratch (device globals: no allocation) ----------------
__device__ float g_means[NSEQ * HIDDEN];                       // pooled means (atomic)
__device__ __align__(16) __nv_bfloat16 g_mhi[NSEQ * HIDDEN];   // means bf16 hi
__device__ __align__(16) __nv_bfloat16 g_mlo[NSEQ * HIDDEN];   // means bf16 lo
__device__ __align__(16) __nv_bfloat16 g_h1hi[NSEQ * FF];      // dense1 out bf16 hi
__device__ __align__(16) __nv_bfloat16 g_h1lo[NSEQ * FF];      // dense1 out bf16 lo
__device__ float g_h2[NSEQ * HIDDEN];                          // dense2 out (atomic)

// ---------------- segment mean pooling (proven round-5/7) ----------------
__global__ __launch_bounds__(192) void pool_kernel(const float* __restrict__ hs,
                                                   const int* __restrict__ lens) {
    __shared__ int   sl[NSEQ];
    __shared__ int   segof[TOKB];
    __shared__ float sinv[NSEQ];

    int tid = threadIdx.x;
    if (tid < NSEQ) {
        int l = lens[tid];
        sl[tid]   = l;
        sinv[tid] = 1.0f / (float)l;
    }
    __syncthreads();
    #pragma unroll
    for (int off = 1; off < NSEQ; off <<= 1) {
        int v = 0;
        if (tid < NSEQ && tid >= off) v = sl[tid - off];
        __syncthreads();
        if (tid < NSEQ) sl[tid] += v;
        __syncthreads();
    }

    int t0 = blockIdx.x * TOKB;
    if (tid < TOKB) {
        int t = t0 + tid;
        int lo = 0, hi = NSEQ - 1;
        while (lo < hi) {
            int mid = (lo + hi) >> 1;
            if (sl[mid] > t) hi = mid; else lo = mid + 1;
        }
        segof[tid] = lo;
    }
    __syncthreads();

    const float4* h4 = (const float4*)hs + (size_t)t0 * (HIDDEN / 4) + tid;

    if (segof[0] == segof[TOKB - 1]) {
        int s = segof[0];
        float4 a0 = make_float4(0.f, 0.f, 0.f, 0.f);
        float4 a1 = a0, a2 = a0, a3 = a0;
        #pragma unroll
        for (int i = 0; i < TOKB; i += 4) {
            float4 v0 = h4[(size_t)(i + 0) * (HIDDEN / 4)];
            float4 v1 = h4[(size_t)(i + 1) * (HIDDEN / 4)];
            float4 v2 = h4[(size_t)(i + 2) * (HIDDEN / 4)];
            float4 v3 = h4[(size_t)(i + 3) * (HIDDEN / 4)];
            a0.x += v0.x; a0.y += v0.y; a0.z += v0.z; a0.w += v0.w;
            a1.x += v1.x; a1.y += v1.y; a1.z += v1.z; a1.w += v1.w;
            a2.x += v2.x; a2.y += v2.y; a2.z += v2.z; a2.w += v2.w;
            a3.x += v3.x; a3.y += v3.y; a3.z += v3.z; a3.w += v3.w;
        }
        float inv = sinv[s];
        float* dst = &g_means[s * HIDDEN + tid * 4];
        atomicAdd(dst + 0, (a0.x + a1.x + a2.x + a3.x) * inv);
        atomicAdd(dst + 1, (a0.y + a1.y + a2.y + a3.y) * inv);
        atomicAdd(dst + 2, (a0.z + a1.z + a2.z + a3.z) * inv);
        atomicAdd(dst + 3, (a0.w + a1.w + a2.w + a3.w) * inv);
    } else {
        float4 acc = make_float4(0.f, 0.f, 0.f, 0.f);
        int cur = segof[0];
        #pragma unroll
        for (int i = 0; i < TOKB; i++) {
            float4 v = h4[(size_t)i * (HIDDEN / 4)];
            int s = segof[i];
            if (s != cur) {
                float inv = sinv[cur];
                float* dst = &g_means[cur * HIDDEN + tid * 4];
                atomicAdd(dst + 0, acc.x * inv); atomicAdd(dst + 1, acc.y * inv);
                atomicAdd(dst + 2, acc.z * inv); atomicAdd(dst + 3, acc.w * inv);
                acc = make_float4(0.f, 0.f, 0.f, 0.f);
                cur = s;
            }
            acc.x += v.x; acc.y += v.y; acc.z += v.z; acc.w += v.w;
        }
        float inv = sinv[cur];
        float* dst = &g_means[cur * HIDDEN + tid * 4];
        atomicAdd(dst + 0, acc.x * inv); atomicAdd(dst + 1, acc.y * inv);
        atomicAdd(dst + 2, acc.z * inv); atomicAdd(dst + 3, acc.w * inv);
    }
}

// ---------------- bf16 hi/lo split of a float4 ----------------
__device__ __forceinline__ void split4(float4 v, unsigned long long& hi, unsigned long long& lo) {
    __nv_bfloat16 h0 = __float2bfloat16(v.x), h1 = __float2bfloat16(v.y);
    __nv_bfloat16 h2 = __float2bfloat16(v.z), h3 = __float2bfloat16(v.w);
    __nv_bfloat16 l0 = __float2bfloat16(v.x - __bfloat162float(h0));
    __nv_bfloat16 l1 = __float2bfloat16(v.y - __bfloat162float(h1));
    __nv_bfloat16 l2 = __float2bfloat16(v.z - __bfloat162float(h2));
    __nv_bfloat16 l3 = __float2bfloat16(v.w - __bfloat162float(h3));
    hi = (unsigned long long)__bfloat16_as_ushort(h0)
       | ((unsigned long long)__bfloat16_as_ushort(h1) << 16)
       | ((unsigned long long)__bfloat16_as_ushort(h2) << 32)
       | ((unsigned long long)__bfloat16_as_ushort(h3) << 48);
    lo = (unsigned long long)__bfloat16_as_ushort(l0)
       | ((unsigned long long)__bfloat16_as_ushort(l1) << 16)
       | ((unsigned long long)__bfloat16_as_ushort(l2) << 32)
       | ((unsigned long long)__bfloat16_as_ushort(l3) << 48);
}

// ---------------- convert means fp32 -> bf16 hi/lo (one-shot) ----------------
__global__ __launch_bounds__(256) void convert_means_kernel() {
    int i = blockIdx.x * 256 + threadIdx.x;          // float4 index
    float4 v = ((const float4*)g_means)[i];
    unsigned long long hi, lo;
    split4(v, hi, lo);
    ((unsigned long long*)g_mhi)[i] = hi;
    ((unsigned long long*)g_mlo)[i] = lo;
}

#define MMA_BF16(C, A0, A1, A2, A3, B0, B1)                                          \
    asm volatile(                                                                    \
        "mma.sync.aligned.m16n8k16.row.col.f32.bf16.bf16.f32 "                       \
        "{%0,%1,%2,%3}, {%4,%5,%6,%7}, {%8,%9}, {%0,%1,%2,%3};"                      \
        : "+f"((C)[0]), "+f"((C)[1]), "+f"((C)[2]), "+f"((C)[3])                     \
        : "r"(A0), "r"(A1), "r"(A2), "r"(A3), "r"(B0), "r"(B1))

// ====== GEMM1: h1[128,3072] = means @ W1^T.  Full K=768, N-tile 32, 96 CTAs ======
// A: bf16 hi/lo preconverted. Epilogue writes bf16 hi/lo directly (CTA owns tile).
__global__ __launch_bounds__(256) void gemm1_kernel(const float* __restrict__ W1) {
    __shared__ __align__(128) unsigned char sm[25600];
    const int SAHI = 0, SALO = 10240, SBHI = 20480, SBLO = 23040;

    int tid = threadIdx.x, wid = tid >> 5, lane = tid & 31;
    int g = lane >> 2, tg = lane & 3;
    int wm = wid >> 1, wn = wid & 1;
    int m0 = wm * 32, nb = wn * 16;
    int n0 = blockIdx.x * 32;

    int ar = tid >> 1, ah = tid & 1;     // A: row 0..127, 32B half
    int brr = tid >> 3, bq = tid & 7;    // B: row 0..31, float4 idx 0..7

    float c[2][2][4];
    #pragma unroll
    for (int i = 0; i < 2; i++)
        #pragma unroll
        for (int j = 0; j < 2; j++)
            #pragma unroll
            for (int r = 0; r < 4; r++) c[i][j][r] = 0.f;

    const __nv_bfloat16* pAh = g_mhi + (size_t)ar * HIDDEN + ah * 16;
    const __nv_bfloat16* pAl = g_mlo + (size_t)ar * HIDDEN + ah * 16;
    const float* pB = W1 + (size_t)(n0 + brr) * HIDDEN + bq * 4;

    uint4 vhi0 = ((const uint4*)pAh)[0], vhi1 = ((const uint4*)pAh)[1];
    uint4 vlo0 = ((const uint4*)pAl)[0], vlo1 = ((const uint4*)pAl)[1];
    float4 bv  = *(const float4*)pB;

    for (int ch = 0; ch < 24; ch++) {
        int aoff = ar * RS + ah * 32;
        *(uint4*)(sm + SAHI + aoff)      = vhi0;
        *(uint4*)(sm + SAHI + aoff + 16) = vhi1;
        *(uint4*)(sm + SALO + aoff)      = vlo0;
        *(uint4*)(sm + SALO + aoff + 16) = vlo1;
        {
            unsigned long long hi, lo;
            split4(bv, hi, lo);
            int boff = brr * RS + bq * 8;
            *(unsigned long long*)(sm + SBHI + boff) = hi;
            *(unsigned long long*)(sm + SBLO + boff) = lo;
        }
        __syncthreads();

        if (ch + 1 < 24) {
            int kk = (ch + 1) * KC;
            vhi0 = ((const uint4*)(pAh + kk))[0]; vhi1 = ((const uint4*)(pAh + kk))[1];
            vlo0 = ((const uint4*)(pAl + kk))[0]; vlo1 = ((const uint4*)(pAl + kk))[1];
            bv   = *(const float4*)(pB + kk);
        }

        #pragma unroll
        for (int ks = 0; ks < 2; ks++) {
            unsigned Ah[2][4], Al[2][4], Bh[2][2], Bl[2][2];
            #pragma unroll
            for (int i = 0; i < 2; i++) {
                int off = (m0 + i * 16 + g) * RS + ks * 32 + tg * 4;
                Ah[i][0] = *(const unsigned*)(sm + SAHI + off);
                Ah[i][1] = *(const unsigned*)(sm + SAHI + off + 8 * RS);
                Ah[i][2] = *(const unsigned*)(sm + SAHI + off + 16);
                Ah[i][3] = *(const unsigned*)(sm + SAHI + off + 8 * RS + 16);
                Al[i][0] = *(const unsigned*)(sm + SALO + off);
                Al[i][1] = *(const unsigned*)(sm + SALO + off + 8 * RS);
                Al[i][2] = *(const unsigned*)(sm + SALO + off + 16);
                Al[i][3] = *(const unsigned*)(sm + SALO + off + 8 * RS + 16);
            }
            #pragma unroll
            for (int j = 0; j < 2; j++) {
                int off = (nb + j * 8 + g) * RS + ks * 32 + tg * 4;
                Bh[j][0] = *(const unsigned*)(sm + SBHI + off);
                Bh[j][1] = *(const unsigned*)(sm + SBHI + off + 16);
                Bl[j][0] = *(const unsigned*)(sm + SBLO + off);
                Bl[j][1] = *(const unsigned*)(sm + SBLO + off + 16);
            }
            #pragma unroll
            for (int i = 0; i < 2; i++)
                #pragma unroll
                for (int j = 0; j < 2; j++) {
                    MMA_BF16(c[i][j], Ah[i][0], Ah[i][1], Ah[i][2], Ah[i][3], Bh[j][0], Bh[j][1]);
                    MMA_BF16(c[i][j], Ah[i][0], Ah[i][1], Ah[i][2], Ah[i][3], Bl[j][0], Bl[j][1]);
                    MMA_BF16(c[i][j], Al[i][0], Al[i][1], Al[i][2], Al[i][3], Bh[j][0], Bh[j][1]);
                }
        }
        __syncthreads();
    }

    // epilogue: write h1 as bf16 hi/lo (this CTA owns the [128 x 32] tile)
    #pragma unroll
    for (int i = 0; i < 2; i++) {
        int R0 = m0 + i * 16 + g, R1 = R0 + 8;
        #pragma unroll
        for (int j = 0; j < 2; j++) {
            int Cc = n0 + nb + j * 8 + tg * 2;
            #pragma unroll
            for (int h = 0; h < 2; h++) {
                int R = h ? R1 : R0;
                float v0 = c[i][j][h * 2 + 0], v1 = c[i][j][h * 2 + 1];
                __nv_bfloat16 h0 = __float2bfloat16(v0), h1 = __float2bfloat16(v1);
                __nv_bfloat16 l0 = __float2bfloat16(v0 - __bfloat162float(h0));
                __nv_bfloat16 l1 = __float2bfloat16(v1 - __bfloat162float(h1));
                unsigned hp = (unsigned)__bfloat16_as_ushort(h0)
                            | ((unsigned)__bfloat16_as_ushort(h1) << 16);
                unsigned lp = (unsigned)__bfloat16_as_ushort(l0)
                            | ((unsigned)__bfloat16_as_ushort(l1) << 16);
                *(unsigned*)&g_h1hi[(size_t)R * FF + Cc] = hp;
                *(unsigned*)&g_h1lo[(size_t)R * FF + Cc] = lp;
            }
        }
    }
}

// ====== GEMM2: h2[128,768] += h1 @ W2^T.  N-tile 64, K-split 16 (192 CTAs) ======
__global__ __launch_bounds__(256) void gemm2_kernel(const float* __restrict__ W2) {
    __shared__ __align__(128) unsigned char sm[30720];
    const int SAHI = 0, SALO = 10240, SBHI = 20480, SBLO = 25600;

    int tid = threadIdx.x, wid = tid >> 5, lane = tid & 31;
    int g = lane >> 2, tg = lane & 3;
    int wm = wid >> 1, wn = wid & 1;
    int m0 = wm * 32, nb = wn * 32;
    int n0 = blockIdx.x * 64;
    int k0 = blockIdx.y * (6 * KC);

    int ar = tid >> 1, ah = tid & 1;
    int br[2], bq[2];
    #pragma unroll
    for (int t = 0; t < 2; t++) { int idx = tid + t * 256; br[t] = idx >> 3; bq[t] = idx & 7; }

    float c[2][4][4];
    #pragma unroll
    for (int i = 0; i < 2; i++)
        #pragma unroll
        for (int j = 0; j < 4; j++)
            #pragma unroll
            for (int r = 0; r < 4; r++) c[i][j][r] = 0.f;

    const __nv_bfloat16* pAh = g_h1hi + (size_t)ar * FF + k0 + ah * 16;
    const __nv_bfloat16* pAl = g_h1lo + (size_t)ar * FF + k0 + ah * 16;

    uint4 vhi0 = ((const uint4*)pAh)[0], vhi1 = ((const uint4*)pAh)[1];
    uint4 vlo0 = ((const uint4*)pAl)[0], vlo1 = ((const uint4*)pAl)[1];
    float4 bv[2];
    #pragma unroll
    for (int t = 0; t < 2; t++)
        bv[t] = *(const float4*)(W2 + (size_t)(n0 + br[t]) * FF + k0 + bq[t] * 4);

    for (int ch = 0; ch < 6; ch++) {
        int aoff = ar * RS + ah * 32;
        *(uint4*)(sm + SAHI + aoff)      = vhi0;
        *(uint4*)(sm + SAHI + aoff + 16) = vhi1;
        *(uint4*)(sm + SALO + aoff)      = vlo0;
        *(uint4*)(sm + SALO + aoff + 16) = vlo1;
        #pragma unroll
        for (int t = 0; t < 2; t++) {
            unsigned long long hi, lo;
            split4(bv[t], hi, lo);
            int boff = br[t] * RS + bq[t] * 8;
            *(unsigned long long*)(sm + SBHI + boff) = hi;
            *(unsigned long long*)(sm + SBLO + boff) = lo;
        }
        __syncthreads();

        if (ch + 1 < 6) {
            int kk = (ch + 1) * KC;
            vhi0 = ((const uint4*)(pAh + kk))[0]; vhi1 = ((const uint4*)(pAh + kk))[1];
            vlo0 = ((const uint4*)(pAl + kk))[0]; vlo1 = ((const uint4*)(pAl + kk))[1];
            #pragma unroll
            for (int t = 0; t < 2; t++)
                bv[t] = *(const float4*)(W2 + (size_t)(n0 + br[t]) * FF + k0 + kk + bq[t] * 4);
        }

        #pragma unroll
        for (int ks = 0; ks < 2; ks++) {
            unsigned Ah[2][4], Al[2][4], Bh[4][2], Bl[4][2];
            #pragma unroll
            for (int i = 0; i < 2; i++) {
                int off = (m0 + i * 16 + g) * RS + ks * 32 + tg * 4;
                Ah[i][0] = *(const unsigned*)(sm + SAHI + off);
                Ah[i][1] = *(const unsigned*)(sm + SAHI + off + 8 * RS);
                Ah[i][2] = *(const unsigned*)(sm + SAHI + off + 16);
                Ah[i][3] = *(const unsigned*)(sm + SAHI + off + 8 * RS + 16);
                Al[i][0] = *(const unsigned*)(sm + SALO + off);
                Al[i][1] = *(const unsigned*)(sm + SALO + off + 8 * RS);
                Al[i][2] = *(const unsigned*)(sm + SALO + off + 16);
                Al[i][3] = *(const unsigned*)(sm + SALO + off + 8 * RS + 16);
            }
            #pragma unroll
            for (int j = 0; j < 4; j++) {
                int off = (nb + j * 8 + g) * RS + ks * 32 + tg * 4;
                Bh[j][0] = *(const unsigned*)(sm + SBHI + off);
                Bh[j][1] = *(const unsigned*)(sm + SBHI + off + 16);
                Bl[j][0] = *(const unsigned*)(sm + SBLO + off);
                Bl[j][1] = *(const unsigned*)(sm + SBLO + off + 16);
            }
            #pragma unroll
            for (int i = 0; i < 2; i++)
                #pragma unroll
                for (int j = 0; j < 4; j++) {
                    MMA_BF16(c[i][j], Ah[i][0], Ah[i][1], Ah[i][2], Ah[i][3], Bh[j][0], Bh[j][1]);
                    MMA_BF16(c[i][j], Ah[i][0], Ah[i][1], Ah[i][2], Ah[i][3], Bl[j][0], Bl[j][1]);
                    MMA_BF16(c[i][j], Al[i][0], Al[i][1], Al[i][2], Al[i][3], Bh[j][0], Bh[j][1]);
                }
        }
        __syncthreads();
    }

    #pragma unroll
    for (int i = 0; i < 2; i++) {
        int R0 = m0 + i * 16 + g, R1 = R0 + 8;
        #pragma unroll
        for (int j = 0; j < 4; j++) {
            int Cc = n0 + nb + j * 8 + tg * 2;
            atomicAdd(&g_h2[(size_t)R0 * HIDDEN + Cc],     c[i][j][0]);
            atomicAdd(&g_h2[(size_t)R0 * HIDDEN + Cc + 1], c[i][j][1]);
            atomicAdd(&g_h2[(size_t)R1 * HIDDEN + Cc],     c[i][j][2]);
            atomicAdd(&g_h2[(size_t)R1 * HIDDEN + Cc + 1], c[i][j][3]);
        }
    }
}

// ---------------- L2 normalize rows ----------------
__global__ __launch_bounds__(192) void norm_kernel(float* __restrict__ out) {
    int s = blockIdx.x, tid = threadIdx.x;   // one float4 per thread
    float4 acc = ((const float4*)(g_h2 + s * HIDDEN))[tid];
    float ss = acc.x * acc.x + acc.y * acc.y + acc.z * acc.z + acc.w * acc.w;

    __shared__ float red[6];
    #pragma unroll
    for (int o = 16; o > 0; o >>= 1) ss += __shfl_xor_sync(0xffffffffu, ss, o);
    if ((tid & 31) == 0) red[tid >> 5] = ss;
    __syncthreads();
    __shared__ float sInv;
    if (tid == 0) {
        float tot = 0.f;
        #pragma unroll
        for (int w = 0; w < 6; w++) tot += red[w];
        sInv = 1.0f / fmaxf(sqrtf(tot), 1e-12f);
    }
    __syncthreads();
    float inv = sInv;
    float4 r = make_float4(acc.x * inv, acc.y * inv, acc.z * inv, acc.w * inv);
    ((float4*)(out + s * HIDDEN))[tid] = r;
}

// ---------------- launch ----------------
extern "C" void kernel_launch(void* const* d_in, const int* in_sizes, int n_in,
                              void* d_out, int out_size) {
    const float* hs   = (const float*)d_in[0];   // [65536, 768] fp32
    const int*   lens = (const int*)  d_in[1];   // [128] int32
    const float* W1   = (const float*)d_in[2];   // [3072, 768] fp32
    const float* W2   = (const float*)d_in[3];   // [768, 3072] fp32
    float* out = (float*)d_out;                  // [128, 768] fp32

    void *pMeans = 0, *pH2 = 0;
    cudaGetSymbolAddress(&pMeans, g_means);
    cudaGetSymbolAddress(&pH2,    g_h2);
    cudaMemsetAsync(pMeans, 0, NSEQ * HIDDEN * sizeof(float));
    cudaMemsetAsync(pH2,    0, NSEQ * HIDDEN * sizeof(float));

    pool_kernel<<<TOKENS / TOKB, 192>>>(hs, lens);
    convert_means_kernel<<<(NSEQ * HIDDEN / 4) / 256, 256>>>();
    gemm1_kernel<<<FF / 32, 256>>>(W1);
    gemm2_kernel<<<dim3(HIDDEN / 64, SPLIT2), 256>>>(W2);
    norm_kernel<<<NSEQ, 192>>>(out);
}

// round 9
// speedup vs baseline: 1.2424x; 1.0515x over previous
#include <cuda_runtime.h>
#include <cuda_bf16.h>

#define HIDDEN 768
#define FF     3072
#define NSEQ   128
#define TOKENS 65536
#define TOKB   32
#define SPLIT1 4      // gemm1 K-split: 768/4 = 192
#define SPLIT2 32     // gemm2 K-split: 3072/32 = 96
#define KC     32     // K floats per chunk
#define RS     80     // smem row stride bytes (32 bf16 = 64B + 16B pad)

// ---------------- scratch (device globals: no allocation) ----------------
__device__ float g_means[NSEQ * HIDDEN];                       // pooled means (atomic)
__device__ __align__(16) __nv_bfloat16 g_mhi[NSEQ * HIDDEN];   // means bf16 hi
__device__ __align__(16) __nv_bfloat16 g_mlo[NSEQ * HIDDEN];   // means bf16 lo
__device__ float g_h1f[NSEQ * FF];                             // dense1 fp32 (atomic)
__device__ __align__(16) __nv_bfloat16 g_h1hi[NSEQ * FF];      // dense1 bf16 hi
__device__ __align__(16) __nv_bfloat16 g_h1lo[NSEQ * FF];      // dense1 bf16 lo
__device__ float g_h2[NSEQ * HIDDEN];                          // dense2 out (atomic)

// ---------------- segment mean pooling (proven) ----------------
__global__ __launch_bounds__(192) void pool_kernel(const float* __restrict__ hs,
                                                   const int* __restrict__ lens) {
    __shared__ int   sl[NSEQ];
    __shared__ int   segof[TOKB];
    __shared__ float sinv[NSEQ];

    int tid = threadIdx.x;
    if (tid < NSEQ) {
        int l = lens[tid];
        sl[tid]   = l;
        sinv[tid] = 1.0f / (float)l;
    }
    __syncthreads();
    #pragma unroll
    for (int off = 1; off < NSEQ; off <<= 1) {
        int v = 0;
        if (tid < NSEQ && tid >= off) v = sl[tid - off];
        __syncthreads();
        if (tid < NSEQ) sl[tid] += v;
        __syncthreads();
    }

    int t0 = blockIdx.x * TOKB;
    if (tid < TOKB) {
        int t = t0 + tid;
        int lo = 0, hi = NSEQ - 1;
        while (lo < hi) {
            int mid = (lo + hi) >> 1;
            if (sl[mid] > t) hi = mid; else lo = mid + 1;
        }
        segof[tid] = lo;
    }
    __syncthreads();

    const float4* h4 = (const float4*)hs + (size_t)t0 * (HIDDEN / 4) + tid;

    if (segof[0] == segof[TOKB - 1]) {
        int s = segof[0];
        float4 a0 = make_float4(0.f, 0.f, 0.f, 0.f);
        float4 a1 = a0, a2 = a0, a3 = a0;
        #pragma unroll
        for (int i = 0; i < TOKB; i += 4) {
            float4 v0 = h4[(size_t)(i + 0) * (HIDDEN / 4)];
            float4 v1 = h4[(size_t)(i + 1) * (HIDDEN / 4)];
            float4 v2 = h4[(size_t)(i + 2) * (HIDDEN / 4)];
            float4 v3 = h4[(size_t)(i + 3) * (HIDDEN / 4)];
            a0.x += v0.x; a0.y += v0.y; a0.z += v0.z; a0.w += v0.w;
            a1.x += v1.x; a1.y += v1.y; a1.z += v1.z; a1.w += v1.w;
            a2.x += v2.x; a2.y += v2.y; a2.z += v2.z; a2.w += v2.w;
            a3.x += v3.x; a3.y += v3.y; a3.z += v3.z; a3.w += v3.w;
        }
        float inv = sinv[s];
        float* dst = &g_means[s * HIDDEN + tid * 4];
        atomicAdd(dst + 0, (a0.x + a1.x + a2.x + a3.x) * inv);
        atomicAdd(dst + 1, (a0.y + a1.y + a2.y + a3.y) * inv);
        atomicAdd(dst + 2, (a0.z + a1.z + a2.z + a3.z) * inv);
        atomicAdd(dst + 3, (a0.w + a1.w + a2.w + a3.w) * inv);
    } else {
        float4 acc = make_float4(0.f, 0.f, 0.f, 0.f);
        int cur = segof[0];
        #pragma unroll
        for (int i = 0; i < TOKB; i++) {
            float4 v = h4[(size_t)i * (HIDDEN / 4)];
            int s = segof[i];
            if (s != cur) {
                float inv = sinv[cur];
                float* dst = &g_means[cur * HIDDEN + tid * 4];
                atomicAdd(dst + 0, acc.x * inv); atomicAdd(dst + 1, acc.y * inv);
                atomicAdd(dst + 2, acc.z * inv); atomicAdd(dst + 3, acc.w * inv);
                acc = make_float4(0.f, 0.f, 0.f, 0.f);
                cur = s;
            }
            acc.x += v.x; acc.y += v.y; acc.z += v.z; acc.w += v.w;
        }
        float inv = sinv[cur];
        float* dst = &g_means[cur * HIDDEN + tid * 4];
        atomicAdd(dst + 0, acc.x * inv); atomicAdd(dst + 1, acc.y * inv);
        atomicAdd(dst + 2, acc.z * inv); atomicAdd(dst + 3, acc.w * inv);
    }
}

// ---------------- bf16 hi/lo split of a float4 ----------------
__device__ __forceinline__ void split4(float4 v, unsigned long long& hi, unsigned long long& lo) {
    __nv_bfloat16 h0 = __float2bfloat16(v.x), h1 = __float2bfloat16(v.y);
    __nv_bfloat16 h2 = __float2bfloat16(v.z), h3 = __float2bfloat16(v.w);
    __nv_bfloat16 l0 = __float2bfloat16(v.x - __bfloat162float(h0));
    __nv_bfloat16 l1 = __float2bfloat16(v.y - __bfloat162float(h1));
    __nv_bfloat16 l2 = __float2bfloat16(v.z - __bfloat162float(h2));
    __nv_bfloat16 l3 = __float2bfloat16(v.w - __bfloat162float(h3));
    hi = (unsigned long long)__bfloat16_as_ushort(h0)
       | ((unsigned long long)__bfloat16_as_ushort(h1) << 16)
       | ((unsigned long long)__bfloat16_as_ushort(h2) << 32)
       | ((unsigned long long)__bfloat16_as_ushort(h3) << 48);
    lo = (unsigned long long)__bfloat16_as_ushort(l0)
       | ((unsigned long long)__bfloat16_as_ushort(l1) << 16)
       | ((unsigned long long)__bfloat16_as_ushort(l2) << 32)
       | ((unsigned long long)__bfloat16_as_ushort(l3) << 48);
}

// ---------------- convert means fp32 -> bf16 hi/lo ----------------
__global__ __launch_bounds__(256) void convert_means_kernel() {
    int i = blockIdx.x * 256 + threadIdx.x;          // float4 index
    float4 v = ((const float4*)g_means)[i];
    unsigned long long hi, lo;
    split4(v, hi, lo);
    ((unsigned long long*)g_mhi)[i] = hi;
    ((unsigned long long*)g_mlo)[i] = lo;
}

// ---------------- convert h1 fp32 -> bf16 hi/lo ----------------
__global__ __launch_bounds__(256) void convert_h1_kernel() {
    int i = blockIdx.x * 256 + threadIdx.x;          // float4 index
    float4 v = ((const float4*)g_h1f)[i];
    unsigned long long hi, lo;
    split4(v, hi, lo);
    ((unsigned long long*)g_h1hi)[i] = hi;
    ((unsigned long long*)g_h1lo)[i] = lo;
}

#define MMA_BF16(C, A0, A1, A2, A3, B0, B1)                                          \
    asm volatile(                                                                    \
        "mma.sync.aligned.m16n8k16.row.col.f32.bf16.bf16.f32 "                       \
        "{%0,%1,%2,%3}, {%4,%5,%6,%7}, {%8,%9}, {%0,%1,%2,%3};"                      \
        : "+f"((C)[0]), "+f"((C)[1]), "+f"((C)[2]), "+f"((C)[3])                     \
        : "r"(A0), "r"(A1), "r"(A2), "r"(A3), "r"(B0), "r"(B1))

// ====== GEMM1: g_h1f += means @ W1^T.  N-tile 32, K-split 4 -> 384 CTAs ======
__global__ __launch_bounds__(256) void gemm1_kernel(const float* __restrict__ W1) {
    __shared__ __align__(128) unsigned char sm[25600];
    const int SAHI = 0, SALO = 10240, SBHI = 20480, SBLO = 23040;

    int tid = threadIdx.x, wid = tid >> 5, lane = tid & 31;
    int g = lane >> 2, tg = lane & 3;
    int wm = wid >> 1, wn = wid & 1;
    int m0 = wm * 32, nb = wn * 16;
    int n0 = blockIdx.x * 32;
    int k0 = blockIdx.y * (6 * KC);                  // 192 K per split

    int ar = tid >> 1, ah = tid & 1;     // A: row 0..127, 32B half
    int brr = tid >> 3, bq = tid & 7;    // B: row 0..31, float4 idx 0..7

    float c[2][2][4];
    #pragma unroll
    for (int i = 0; i < 2; i++)
        #pragma unroll
        for (int j = 0; j < 2; j++)
            #pragma unroll
            for (int r = 0; r < 4; r++) c[i][j][r] = 0.f;

    const __nv_bfloat16* pAh = g_mhi + (size_t)ar * HIDDEN + k0 + ah * 16;
    const __nv_bfloat16* pAl = g_mlo + (size_t)ar * HIDDEN + k0 + ah * 16;
    const float* pB = W1 + (size_t)(n0 + brr) * HIDDEN + k0 + bq * 4;

    uint4 vhi0 = ((const uint4*)pAh)[0], vhi1 = ((const uint4*)pAh)[1];
    uint4 vlo0 = ((const uint4*)pAl)[0], vlo1 = ((const uint4*)pAl)[1];
    float4 bv  = *(const float4*)pB;

    for (int ch = 0; ch < 6; ch++) {
        int aoff = ar * RS + ah * 32;
        *(uint4*)(sm + SAHI + aoff)      = vhi0;
        *(uint4*)(sm + SAHI + aoff + 16) = vhi1;
        *(uint4*)(sm + SALO + aoff)      = vlo0;
        *(uint4*)(sm + SALO + aoff + 16) = vlo1;
        {
            unsigned long long hi, lo;
            split4(bv, hi, lo);
            int boff = brr * RS + bq * 8;
            *(unsigned long long*)(sm + SBHI + boff) = hi;
            *(unsigned long long*)(sm + SBLO + boff) = lo;
        }
        __syncthreads();

        if (ch + 1 < 6) {
            int kk = (ch + 1) * KC;
            vhi0 = ((const uint4*)(pAh + kk))[0]; vhi1 = ((const uint4*)(pAh + kk))[1];
            vlo0 = ((const uint4*)(pAl + kk))[0]; vlo1 = ((const uint4*)(pAl + kk))[1];
            bv   = *(const float4*)(pB + kk);
        }

        #pragma unroll
        for (int ks = 0; ks < 2; ks++) {
            unsigned Ah[2][4], Al[2][4], Bh[2][2], Bl[2][2];
            #pragma unroll
            for (int i = 0; i < 2; i++) {
                int off = (m0 + i * 16 + g) * RS + ks * 32 + tg * 4;
                Ah[i][0] = *(const unsigned*)(sm + SAHI + off);
                Ah[i][1] = *(const unsigned*)(sm + SAHI + off + 8 * RS);
                Ah[i][2] = *(const unsigned*)(sm + SAHI + off + 16);
                Ah[i][3] = *(const unsigned*)(sm + SAHI + off + 8 * RS + 16);
                Al[i][0] = *(const unsigned*)(sm + SALO + off);
                Al[i][1] = *(const unsigned*)(sm + SALO + off + 8 * RS);
                Al[i][2] = *(const unsigned*)(sm + SALO + off + 16);
                Al[i][3] = *(const unsigned*)(sm + SALO + off + 8 * RS + 16);
            }
            #pragma unroll
            for (int j = 0; j < 2; j++) {
                int off = (nb + j * 8 + g) * RS + ks * 32 + tg * 4;
                Bh[j][0] = *(const unsigned*)(sm + SBHI + off);
                Bh[j][1] = *(const unsigned*)(sm + SBHI + off + 16);
                Bl[j][0] = *(const unsigned*)(sm + SBLO + off);
                Bl[j][1] = *(const unsigned*)(sm + SBLO + off + 16);
            }
            #pragma unroll
            for (int i = 0; i < 2; i++)
                #pragma unroll
                for (int j = 0; j < 2; j++) {
                    MMA_BF16(c[i][j], Ah[i][0], Ah[i][1], Ah[i][2], Ah[i][3], Bh[j][0], Bh[j][1]);
                    MMA_BF16(c[i][j], Ah[i][0], Ah[i][1], Ah[i][2], Ah[i][3], Bl[j][0], Bl[j][1]);
                    MMA_BF16(c[i][j], Al[i][0], Al[i][1], Al[i][2], Al[i][3], Bh[j][0], Bh[j][1]);
                }
        }
        __syncthreads();
    }

    // epilogue: fp32 atomic accumulate (4 K-splits target same tile)
    #pragma unroll
    for (int i = 0; i < 2; i++) {
        int R0 = m0 + i * 16 + g, R1 = R0 + 8;
        #pragma unroll
        for (int j = 0; j < 2; j++) {
            int Cc = n0 + nb + j * 8 + tg * 2;
            atomicAdd(&g_h1f[(size_t)R0 * FF + Cc],     c[i][j][0]);
            atomicAdd(&g_h1f[(size_t)R0 * FF + Cc + 1], c[i][j][1]);
            atomicAdd(&g_h1f[(size_t)R1 * FF + Cc],     c[i][j][2]);
            atomicAdd(&g_h1f[(size_t)R1 * FF + Cc + 1], c[i][j][3]);
        }
    }
}

// ====== GEMM2: g_h2 += h1 @ W2^T.  N-tile 64, K-split 32 -> 384 CTAs ======
__global__ __launch_bounds__(256) void gemm2_kernel(const float* __restrict__ W2) {
    __shared__ __align__(128) unsigned char sm[30720];
    const int SAHI = 0, SALO = 10240, SBHI = 20480, SBLO = 25600;

    int tid = threadIdx.x, wid = tid >> 5, lane = tid & 31;
    int g = lane >> 2, tg = lane & 3;
    int wm = wid >> 1, wn = wid & 1;
    int m0 = wm * 32, nb = wn * 32;
    int n0 = blockIdx.x * 64;
    int k0 = blockIdx.y * (3 * KC);                  // 96 K per split

    int ar = tid >> 1, ah = tid & 1;
    int br[2], bq[2];
    #pragma unroll
    for (int t = 0; t < 2; t++) { int idx = tid + t * 256; br[t] = idx >> 3; bq[t] = idx & 7; }

    float c[2][4][4];
    #pragma unroll
    for (int i = 0; i < 2; i++)
        #pragma unroll
        for (int j = 0; j < 4; j++)
            #pragma unroll
            for (int r = 0; r < 4; r++) c[i][j][r] = 0.f;

    const __nv_bfloat16* pAh = g_h1hi + (size_t)ar * FF + k0 + ah * 16;
    const __nv_bfloat16* pAl = g_h1lo + (size_t)ar * FF + k0 + ah * 16;

    uint4 vhi0 = ((const uint4*)pAh)[0], vhi1 = ((const uint4*)pAh)[1];
    uint4 vlo0 = ((const uint4*)pAl)[0], vlo1 = ((const uint4*)pAl)[1];
    float4 bv[2];
    #pragma unroll
    for (int t = 0; t < 2; t++)
        bv[t] = *(const float4*)(W2 + (size_t)(n0 + br[t]) * FF + k0 + bq[t] * 4);

    for (int ch = 0; ch < 3; ch++) {
        int aoff = ar * RS + ah * 32;
        *(uint4*)(sm + SAHI + aoff)      = vhi0;
        *(uint4*)(sm + SAHI + aoff + 16) = vhi1;
        *(uint4*)(sm + SALO + aoff)      = vlo0;
        *(uint4*)(sm + SALO + aoff + 16) = vlo1;
        #pragma unroll
        for (int t = 0; t < 2; t++) {
            unsigned long long hi, lo;
            split4(bv[t], hi, lo);
            int boff = br[t] * RS + bq[t] * 8;
            *(unsigned long long*)(sm + SBHI + boff) = hi;
            *(unsigned long long*)(sm + SBLO + boff) = lo;
        }
        __syncthreads();

        if (ch + 1 < 3) {
            int kk = (ch + 1) * KC;
            vhi0 = ((const uint4*)(pAh + kk))[0]; vhi1 = ((const uint4*)(pAh + kk))[1];
            vlo0 = ((const uint4*)(pAl + kk))[0]; vlo1 = ((const uint4*)(pAl + kk))[1];
            #pragma unroll
            for (int t = 0; t < 2; t++)
                bv[t] = *(const float4*)(W2 + (size_t)(n0 + br[t]) * FF + k0 + kk + bq[t] * 4);
        }

        #pragma unroll
        for (int ks = 0; ks < 2; ks++) {
            unsigned Ah[2][4], Al[2][4], Bh[4][2], Bl[4][2];
            #pragma unroll
            for (int i = 0; i < 2; i++) {
                int off = (m0 + i * 16 + g) * RS + ks * 32 + tg * 4;
                Ah[i][0] = *(const unsigned*)(sm + SAHI + off);
                Ah[i][1] = *(const unsigned*)(sm + SAHI + off + 8 * RS);
                Ah[i][2] = *(const unsigned*)(sm + SAHI + off + 16);
                Ah[i][3] = *(const unsigned*)(sm + SAHI + off + 8 * RS + 16);
                Al[i][0] = *(const unsigned*)(sm + SALO + off);
                Al[i][1] = *(const unsigned*)(sm + SALO + off + 8 * RS);
                Al[i][2] = *(const unsigned*)(sm + SALO + off + 16);
                Al[i][3] = *(const unsigned*)(sm + SALO + off + 8 * RS + 16);
            }
            #pragma unroll
            for (int j = 0; j < 4; j++) {
                int off = (nb + j * 8 + g) * RS + ks * 32 + tg * 4;
                Bh[j][0] = *(const unsigned*)(sm + SBHI + off);
                Bh[j][1] = *(const unsigned*)(sm + SBHI + off + 16);
                Bl[j][0] = *(const unsigned*)(sm + SBLO + off);
                Bl[j][1] = *(const unsigned*)(sm + SBLO + off + 16);
            }
            #pragma unroll
            for (int i = 0; i < 2; i++)
                #pragma unroll
                for (int j = 0; j < 4; j++) {
                    MMA_BF16(c[i][j], Ah[i][0], Ah[i][1], Ah[i][2], Ah[i][3], Bh[j][0], Bh[j][1]);
                    MMA_BF16(c[i][j], Ah[i][0], Ah[i][1], Ah[i][2], Ah[i][3], Bl[j][0], Bl[j][1]);
                    MMA_BF16(c[i][j], Al[i][0], Al[i][1], Al[i][2], Al[i][3], Bh[j][0], Bh[j][1]);
                }
        }
        __syncthreads();
    }

    #pragma unroll
    for (int i = 0; i < 2; i++) {
        int R0 = m0 + i * 16 + g, R1 = R0 + 8;
        #pragma unroll
        for (int j = 0; j < 4; j++) {
            int Cc = n0 + nb + j * 8 + tg * 2;
            atomicAdd(&g_h2[(size_t)R0 * HIDDEN + Cc],     c[i][j][0]);
            atomicAdd(&g_h2[(size_t)R0 * HIDDEN + Cc + 1], c[i][j][1]);
            atomicAdd(&g_h2[(size_t)R1 * HIDDEN + Cc],     c[i][j][2]);
            atomicAdd(&g_h2[(size_t)R1 * HIDDEN + Cc + 1], c[i][j][3]);
        }
    }
}

// ---------------- L2 normalize rows ----------------
__global__ __launch_bounds__(192) void norm_kernel(float* __restrict__ out) {
    int s = blockIdx.x, tid = threadIdx.x;   // one float4 per thread
    float4 acc = ((const float4*)(g_h2 + s * HIDDEN))[tid];
    float ss = acc.x * acc.x + acc.y * acc.y + acc.z * acc.z + acc.w * acc.w;

    __shared__ float red[6];
    #pragma unroll
    for (int o = 16; o > 0; o >>= 1) ss += __shfl_xor_sync(0xffffffffu, ss, o);
    if ((tid & 31) == 0) red[tid >> 5] = ss;
    __syncthreads();
    __shared__ float sInv;
    if (tid == 0) {
        float tot = 0.f;
        #pragma unroll
        for (int w = 0; w < 6; w++) tot += red[w];
        sInv = 1.0f / fmaxf(sqrtf(tot), 1e-12f);
    }
    __syncthreads();
    float inv = sInv;
    float4 r = make_float4(acc.x * inv, acc.y * inv, acc.z * inv, acc.w * inv);
    ((float4*)(out + s * HIDDEN))[tid] = r;
}

// ---------------- launch ----------------
extern "C" void kernel_launch(void* const* d_in, const int* in_sizes, int n_in,
                              void* d_out, int out_size) {
    const float* hs   = (const float*)d_in[0];   // [65536, 768] fp32
    const int*   lens = (const int*)  d_in[1];   // [128] int32
    const float* W1   = (const float*)d_in[2];   // [3072, 768] fp32
    const float* W2   = (const float*)d_in[3];   // [768, 3072] fp32
    float* out = (float*)d_out;                  // [128, 768] fp32

    void *pMeans = 0, *pH1f = 0, *pH2 = 0;
    cudaGetSymbolAddress(&pMeans, g_means);
    cudaGetSymbolAddress(&pH1f,   g_h1f);
    cudaGetSymbolAddress(&pH2,    g_h2);
    cudaMemsetAsync(pMeans, 0, NSEQ * HIDDEN * sizeof(float));
    cudaMemsetAsync(pH1f,   0, NSEQ * FF     * sizeof(float));
    cudaMemsetAsync(pH2,    0, NSEQ * HIDDEN * sizeof(float));

    pool_kernel<<<TOKENS / TOKB, 192>>>(hs, lens);
    convert_means_kernel<<<(NSEQ * HIDDEN / 4) / 256, 256>>>();
    gemm1_kernel<<<dim3(FF / 32, SPLIT1), 256>>>(W1);
    convert_h1_kernel<<<(NSEQ * FF / 4) / 256, 256>>>();
    gemm2_kernel<<<dim3(HIDDEN / 64, SPLIT2), 256>>>(W2);
    norm_kernel<<<NSEQ, 192>>>(out);
}